// round 1
// baseline (speedup 1.0000x reference)
#include <cuda_runtime.h>
#include <cuda_bf16.h>

// Problem constants
#define BB 2
#define SS 2048
#define DD 1024
#define HH 16
#define HD 64
#define WW 31
#define NC 1024   // H*HD = E = D = 1024

// Scratch (device globals; no allocation allowed)
__device__ float g_Wqf[1024 * 1024];
__device__ float g_Wkf[1024 * 1024];
__device__ float g_Wvf[1024 * 1024];
__device__ float g_qh  [SS * NC];
__device__ float g_posk[SS * NC];
__device__ float g_posv[SS * NC];
__device__ float g_fsqk[SS * NC];
__device__ float g_fsqv[SS * NC];
__device__ float g_xk  [BB * SS * NC];
__device__ float g_xv  [BB * SS * NC];
__device__ float g_att [BB * SS * NC];

// ---------------------------------------------------------------------------
// Transpose (H, D, HD) weights into (D, H*HD) so projections are plain GEMMs.
// ---------------------------------------------------------------------------
__global__ void transpose_w(const float* __restrict__ Wq,
                            const float* __restrict__ Wk,
                            const float* __restrict__ Wv) {
    int idx = blockIdx.x * 256 + threadIdx.x;   // over 1024*1024
    int d = idx >> 10;
    int c = idx & 1023;
    int h = c >> 6, e = c & 63;
    int src = ((h << 10) + d) * 64 + e;         // h*D*HD + d*HD + e
    g_Wqf[idx] = Wq[src];
    g_Wkf[idx] = Wk[src];
    g_Wvf[idx] = Wv[src];
}

// ---------------------------------------------------------------------------
// SGEMM: C[M,N] = A[M,K] @ B[K,N] + bias[N]
// 128x128 block tile, BK=8, 8x8 per-thread micro-tile, 256 threads.
// M % 128 == 0, N % 128 == 0, K % 8 == 0 guaranteed by caller.
// ---------------------------------------------------------------------------
__global__ __launch_bounds__(256) void sgemm_bias(
    const float* __restrict__ A, const float* __restrict__ B,
    const float* __restrict__ bias, float* __restrict__ C,
    int M, int N, int K)
{
    __shared__ float As[8][128];
    __shared__ float Bs[8][128];

    const int tid  = threadIdx.x;
    const int brow = blockIdx.y;
    const int bcol = blockIdx.x;

    const float* Ab = A + (size_t)brow * 128 * K;
    const float* Bb = B + bcol * 128;

    // A tile loader: 128x8 floats -> one float4 per thread
    const int a_r = tid >> 1;             // 0..127
    const int a_c = (tid & 1) << 2;       // 0 or 4
    // B tile loader: 8x128 floats -> one float4 per thread
    const int b_r = tid >> 5;             // 0..7
    const int b_c = (tid & 31) << 2;      // 0..124
    // compute micro-tile origin
    const int t_r = (tid >> 4) << 3;      // 0..120
    const int t_c = (tid & 15) << 3;      // 0..120

    float acc[8][8];
    #pragma unroll
    for (int i = 0; i < 8; i++)
        #pragma unroll
        for (int j = 0; j < 8; j++) acc[i][j] = 0.f;

    for (int k0 = 0; k0 < K; k0 += 8) {
        float4 av = *(const float4*)(Ab + (size_t)a_r * K + k0 + a_c);
        As[a_c + 0][a_r] = av.x;
        As[a_c + 1][a_r] = av.y;
        As[a_c + 2][a_r] = av.z;
        As[a_c + 3][a_r] = av.w;
        *(float4*)(&Bs[b_r][b_c]) = *(const float4*)(Bb + (size_t)(k0 + b_r) * N + b_c);
        __syncthreads();

        #pragma unroll
        for (int kk = 0; kk < 8; kk++) {
            float ar[8], br[8];
            #pragma unroll
            for (int i = 0; i < 8; i++) ar[i] = As[kk][t_r + i];
            #pragma unroll
            for (int j = 0; j < 8; j++) br[j] = Bs[kk][t_c + j];
            #pragma unroll
            for (int i = 0; i < 8; i++)
                #pragma unroll
                for (int j = 0; j < 8; j++)
                    acc[i][j] += ar[i] * br[j];
        }
        __syncthreads();
    }

    const int col0 = bcol * 128 + t_c;
    float bsv[8];
    #pragma unroll
    for (int j = 0; j < 8; j++) bsv[j] = bias[col0 + j];

    #pragma unroll
    for (int i = 0; i < 8; i++) {
        const size_t row = (size_t)(brow * 128 + t_r + i);
        float4 v0 = make_float4(acc[i][0] + bsv[0], acc[i][1] + bsv[1],
                                acc[i][2] + bsv[2], acc[i][3] + bsv[3]);
        float4 v1 = make_float4(acc[i][4] + bsv[4], acc[i][5] + bsv[5],
                                acc[i][6] + bsv[6], acc[i][7] + bsv[7]);
        *(float4*)(&C[row * N + col0])     = v0;
        *(float4*)(&C[row * N + col0 + 4]) = v1;
    }
}

// ---------------------------------------------------------------------------
// Attention: one warp per (b, h, s). 33 keys of dim 64.
// Window key k (0..30) at position s is xk[b, s+k-15]; out-of-range rows of
// the zero-padded input project to exactly the bias (bk / bv).
// Key 31 = pos projection, key 32 = fsq projection (batch-independent).
// ---------------------------------------------------------------------------
__global__ __launch_bounds__(256) void attn_kernel(
    const float* __restrict__ bk, const float* __restrict__ bv)
{
    const int gw   = (blockIdx.x * 256 + threadIdx.x) >> 5;  // 0 .. B*H*S-1
    const int lane = threadIdx.x & 31;
    const int s = gw & (SS - 1);
    const int h = (gw >> 11) & (HH - 1);
    const int b = gw >> 15;

    const int e0 = (h << 6) + lane;
    const int e1 = e0 + 32;

    const float* qrow = g_qh + (size_t)s * NC;
    const float  q0 = qrow[e0], q1 = qrow[e1];

    float sc[33];

    #pragma unroll
    for (int k = 0; k < WW; k++) {
        const int t = s + k - 15;
        float k0, k1;
        if ((unsigned)t < SS) {
            const float* kr = g_xk + (size_t)((b << 11) + t) * NC;
            k0 = kr[e0]; k1 = kr[e1];
        } else {
            k0 = bk[e0]; k1 = bk[e1];
        }
        float p = q0 * k0 + q1 * k1;
        #pragma unroll
        for (int o = 16; o; o >>= 1) p += __shfl_xor_sync(0xffffffffu, p, o);
        sc[k] = p * 0.125f;
    }
    {
        const float* kr = g_posk + (size_t)s * NC;
        float p = q0 * kr[e0] + q1 * kr[e1];
        #pragma unroll
        for (int o = 16; o; o >>= 1) p += __shfl_xor_sync(0xffffffffu, p, o);
        sc[31] = p * 0.125f;
    }
    {
        const float* kr = g_fsqk + (size_t)s * NC;
        float p = q0 * kr[e0] + q1 * kr[e1];
        #pragma unroll
        for (int o = 16; o; o >>= 1) p += __shfl_xor_sync(0xffffffffu, p, o);
        sc[32] = p * 0.125f;
    }

    float m = sc[0];
    #pragma unroll
    for (int k = 1; k < 33; k++) m = fmaxf(m, sc[k]);
    float denom = 0.f;
    #pragma unroll
    for (int k = 0; k < 33; k++) { sc[k] = expf(sc[k] - m); denom += sc[k]; }
    const float inv = 1.f / denom;

    float o0 = 0.f, o1 = 0.f;
    #pragma unroll
    for (int k = 0; k < WW; k++) {
        const int t = s + k - 15;
        float v0, v1;
        if ((unsigned)t < SS) {
            const float* vr = g_xv + (size_t)((b << 11) + t) * NC;
            v0 = vr[e0]; v1 = vr[e1];
        } else {
            v0 = bv[e0]; v1 = bv[e1];
        }
        o0 += sc[k] * v0; o1 += sc[k] * v1;
    }
    {
        const float* vr = g_posv + (size_t)s * NC;
        o0 += sc[31] * vr[e0]; o1 += sc[31] * vr[e1];
    }
    {
        const float* vr = g_fsqv + (size_t)s * NC;
        o0 += sc[32] * vr[e0]; o1 += sc[32] * vr[e1];
    }

    float* orow = g_att + (size_t)((b << 11) + s) * NC;
    orow[e0] = o0 * inv;
    orow[e1] = o1 * inv;
}

// ---------------------------------------------------------------------------
// Launch
// Inputs (metadata order): x, fsq, pos, Wq, bq, Wk, bk, Wv, bv, Wo, bo
// ---------------------------------------------------------------------------
extern "C" void kernel_launch(void* const* d_in, const int* in_sizes, int n_in,
                              void* d_out, int out_size) {
    const float* x   = (const float*)d_in[0];
    const float* fsq = (const float*)d_in[1];
    const float* pos = (const float*)d_in[2];
    const float* Wq  = (const float*)d_in[3];
    const float* bq  = (const float*)d_in[4];
    const float* Wk  = (const float*)d_in[5];
    const float* bk  = (const float*)d_in[6];
    const float* Wv  = (const float*)d_in[7];
    const float* bv  = (const float*)d_in[8];
    const float* Wo  = (const float*)d_in[9];
    const float* bo  = (const float*)d_in[10];
    float* out = (float*)d_out;

    float *Wqf, *Wkf, *Wvf, *qh, *posk, *posv, *fsqk, *fsqv, *xk, *xv, *att;
    cudaGetSymbolAddress((void**)&Wqf,  g_Wqf);
    cudaGetSymbolAddress((void**)&Wkf,  g_Wkf);
    cudaGetSymbolAddress((void**)&Wvf,  g_Wvf);
    cudaGetSymbolAddress((void**)&qh,   g_qh);
    cudaGetSymbolAddress((void**)&posk, g_posk);
    cudaGetSymbolAddress((void**)&posv, g_posv);
    cudaGetSymbolAddress((void**)&fsqk, g_fsqk);
    cudaGetSymbolAddress((void**)&fsqv, g_fsqv);
    cudaGetSymbolAddress((void**)&xk,   g_xk);
    cudaGetSymbolAddress((void**)&xv,   g_xv);
    cudaGetSymbolAddress((void**)&att,  g_att);

    transpose_w<<<4096, 256>>>(Wq, Wk, Wv);

    dim3 g2(8, 16);   // M=2048
    dim3 g4(8, 32);   // M=4096
    sgemm_bias<<<g2, 256>>>(fsq, Wqf, bq, qh,   SS,      NC, DD);
    sgemm_bias<<<g2, 256>>>(pos, Wkf, bk, posk, SS,      NC, DD);
    sgemm_bias<<<g2, 256>>>(pos, Wvf, bv, posv, SS,      NC, DD);
    sgemm_bias<<<g2, 256>>>(fsq, Wkf, bk, fsqk, SS,      NC, DD);
    sgemm_bias<<<g2, 256>>>(fsq, Wvf, bv, fsqv, SS,      NC, DD);
    sgemm_bias<<<g4, 256>>>(x,   Wkf, bk, xk,   BB * SS, NC, DD);
    sgemm_bias<<<g4, 256>>>(x,   Wvf, bv, xv,   BB * SS, NC, DD);

    attn_kernel<<<(BB * HH * SS) / 8, 256>>>(bk, bv);

    sgemm_bias<<<g4, 256>>>(att, Wo, bo, out, BB * SS, NC, DD);
}

// round 4
// speedup vs baseline: 1.8411x; 1.8411x over previous
#include <cuda_runtime.h>
#include <cuda_bf16.h>
#include <cstdint>

#define BB 2
#define SS 2048
#define HH 16
#define WW 31
#define K2 3072            // interleave-3: 1024 fp32 -> 3072 bf16
#define STAGES 4
#define AROWB 80           // padded smem row bytes (32 bf16 + 8 pad)
#define STAGEB (128 * AROWB)
#define STAGE2 (2 * STAGEB)

// ---------------- device scratch -------------------------------------------
__device__ __align__(16) __nv_bfloat16 g_afsq[2048u * K2];
__device__ __align__(16) __nv_bfloat16 g_apos[2048u * K2];
__device__ __align__(16) __nv_bfloat16 g_ax  [4096u * K2];
__device__ __align__(16) __nv_bfloat16 g_aatt[4096u * K2];
__device__ __align__(16) __nv_bfloat16 g_bqkv[3072u * K2];
__device__ __align__(16) __nv_bfloat16 g_bo  [1024u * K2];
__device__ float g_C1 [2048u * 3072];   // [qh | fsqk | fsqv]
__device__ float g_C2 [2048u * 2048];   // [posk | posv]
__device__ float g_C3 [4096u * 2048];   // [xk | xv]
__device__ float g_att[4096u * 1024];
__device__ float g_bias3[3072];

// ---------------- helpers ---------------------------------------------------
__device__ __forceinline__ uint32_t smem_to_u32(const void* p) {
    uint32_t a;
    asm("{ .reg .u64 t; cvta.to.shared.u64 t, %1; cvt.u32.u64 %0, t; }"
        : "=r"(a) : "l"(p));
    return a;
}
__device__ __forceinline__ void cp16(uint32_t s, const void* g) {
    asm volatile("cp.async.cg.shared.global [%0], [%1], 16;" :: "r"(s), "l"(g));
}
__device__ __forceinline__ uint32_t lds32(uint32_t a) {
    uint32_t v;
    asm volatile("ld.shared.b32 %0, [%1];" : "=r"(v) : "r"(a));
    return v;
}
__device__ __forceinline__ void mma16816(float* c, const uint32_t* a, const uint32_t* b) {
    asm volatile(
        "mma.sync.aligned.m16n8k16.row.col.f32.bf16.bf16.f32 "
        "{%0,%1,%2,%3}, {%4,%5,%6,%7}, {%8,%9}, {%0,%1,%2,%3};"
        : "+f"(c[0]), "+f"(c[1]), "+f"(c[2]), "+f"(c[3])
        : "r"(a[0]), "r"(a[1]), "r"(a[2]), "r"(a[3]), "r"(b[0]), "r"(b[1]));
}
__device__ __forceinline__ void split2(float a, unsigned short& h, unsigned short& l) {
    __nv_bfloat16 hb = __float2bfloat16_rn(a);
    __nv_bfloat16 lb = __float2bfloat16_rn(a - __bfloat162float(hb));
    h = __bfloat16_as_ushort(hb);
    l = __bfloat16_as_ushort(lb);
}

// pack 8 fp32 -> 24 bf16 triples -> 3x uint4 stores at dst (16B aligned)
// a_side: (h, l, h);  b_side: (h, h, l)
template <bool ASIDE>
__device__ __forceinline__ void pack_triples(const float* f, __nv_bfloat16* dst) {
    unsigned short t[24];
#pragma unroll
    for (int i = 0; i < 8; i++) {
        unsigned short h, l;
        split2(f[i], h, l);
        if (ASIDE) { t[3 * i] = h; t[3 * i + 1] = l; t[3 * i + 2] = h; }
        else       { t[3 * i] = h; t[3 * i + 1] = h; t[3 * i + 2] = l; }
    }
    uint32_t u[12];
#pragma unroll
    for (int j = 0; j < 12; j++)
        u[j] = (uint32_t)t[2 * j] | ((uint32_t)t[2 * j + 1] << 16);
    uint4* q = (uint4*)dst;
    q[0] = make_uint4(u[0], u[1], u[2], u[3]);
    q[1] = make_uint4(u[4], u[5], u[6], u[7]);
    q[2] = make_uint4(u[8], u[9], u[10], u[11]);
}

// ---------------- prep kernels ----------------------------------------------
// X[M][1024] fp32 -> O[M][3072] bf16 (h,l,h)
__global__ __launch_bounds__(256) void split_a(const float* __restrict__ X,
                                               __nv_bfloat16* __restrict__ O) {
    int idx = blockIdx.x * 256 + threadIdx.x;   // M*128
    int r = idx >> 7, k8 = idx & 127;
    const float4* p = (const float4*)(X + (size_t)r * 1024 + k8 * 8);
    float4 v0 = p[0], v1 = p[1];
    float f[8] = {v0.x, v0.y, v0.z, v0.w, v1.x, v1.y, v1.z, v1.w};
    pack_triples<true>(f, O + (size_t)r * K2 + k8 * 24);
}

// B rows n (0..3071): n<1024 -> Wq, <2048 -> Wk, else Wv.  W[h][k][e], (h,h,l)
__global__ __launch_bounds__(256) void split_wqkv(const float* __restrict__ Wq,
                                                  const float* __restrict__ Wk,
                                                  const float* __restrict__ Wv) {
    int idx = blockIdx.x * 256 + threadIdx.x;   // 3072*128
    int n = idx >> 7, kb = idx & 127;
    int sel = n >> 10, nn = n & 1023, h = nn >> 6, e = nn & 63;
    const float* W = sel == 0 ? Wq : (sel == 1 ? Wk : Wv);
    const float* src = W + ((size_t)h << 16) + (size_t)(kb * 8) * 64 + e;
    float f[8];
#pragma unroll
    for (int i = 0; i < 8; i++) f[i] = src[i * 64];
    pack_triples<false>(f, g_bqkv + (size_t)n * K2 + kb * 24);
}

// Wo[k][n] -> rows n, (h,h,l)
__global__ __launch_bounds__(256) void split_wo(const float* __restrict__ Wo) {
    int idx = blockIdx.x * 256 + threadIdx.x;   // 1024*128
    int n = idx >> 7, kb = idx & 127;
    float f[8];
#pragma unroll
    for (int i = 0; i < 8; i++) f[i] = Wo[(size_t)(kb * 8 + i) * 1024 + n];
    pack_triples<false>(f, g_bo + (size_t)n * K2 + kb * 24);
}

__global__ void fuse_bias(const float* bq, const float* bk, const float* bv) {
    int i = blockIdx.x * 256 + threadIdx.x;
    if (i < 3072)
        g_bias3[i] = i < 1024 ? bq[i] : (i < 2048 ? bk[i - 1024] : bv[i - 2048]);
}

// ---------------- bf16 mma.sync GEMM ----------------------------------------
// C[M,Ntot](+bias) = A[M,K2] @ B[N,K2]^T.  CTA 128x128, BK=32, 8 warps (2x4),
// warp tile 64x32, m16n8k16, 4-stage cp.async pipeline.
__global__ __launch_bounds__(256) void gemm_bf16i(
    const __nv_bfloat16* __restrict__ A, const __nv_bfloat16* __restrict__ B,
    const float* __restrict__ bias, float* __restrict__ C, int Ntot)
{
    extern __shared__ __align__(16) unsigned char sm[];
    const int tid = threadIdx.x;
    const int wid = tid >> 5, lane = tid & 31;
    const int m0 = blockIdx.y * 128, n0 = blockIdx.x * 128;
    const int wr = wid >> 2, wc = wid & 3;    // warp grid 2x4

    const unsigned char* Ag = (const unsigned char*)A + (size_t)m0 * (K2 * 2);
    const unsigned char* Bg = (const unsigned char*)B + (size_t)n0 * (K2 * 2);

    const uint32_t smb = smem_to_u32(sm);
    const int lr = tid >> 1, lh = tid & 1;            // loader: row, 32B half
    const uint32_t adst = smb + lr * AROWB + lh * 32;
    const uint32_t bdst = adst + STAGEB;
    const size_t goff = (size_t)lr * (K2 * 2) + lh * 32;

    auto load_stage = [&](int st, int c) {
        const unsigned char* ag = Ag + goff + c * 64;
        const unsigned char* bg = Bg + goff + c * 64;
        uint32_t d = st * STAGE2;
        cp16(adst + d, ag);       cp16(adst + d + 16, ag + 16);
        cp16(bdst + d, bg);       cp16(bdst + d + 16, bg + 16);
        asm volatile("cp.async.commit_group;" ::: "memory");
    };

    float acc[4][4][4];
#pragma unroll
    for (int i = 0; i < 4; i++)
#pragma unroll
        for (int j = 0; j < 4; j++)
#pragma unroll
            for (int k = 0; k < 4; k++) acc[i][j][k] = 0.f;

#pragma unroll
    for (int s = 0; s < STAGES - 1; s++) load_stage(s, s);

    const int NCHUNK = K2 / 32;   // 96
    for (int c = 0; c < NCHUNK; c++) {
        const int st = c & (STAGES - 1);
        asm volatile("cp.async.wait_group %0;" :: "n"(STAGES - 2) : "memory");
        __syncthreads();
        if (c + STAGES - 1 < NCHUNK) load_stage((c + STAGES - 1) & (STAGES - 1), c + STAGES - 1);

        const uint32_t abase = smb + st * STAGE2;
        const uint32_t bbase = abase + STAGEB;
#pragma unroll
        for (int ks = 0; ks < 2; ks++) {
            const uint32_t kb = ks * 32 + (lane & 3) * 4;   // byte offset of this thread's k-pair
            uint32_t a[4][4], b[4][2];
#pragma unroll
            for (int mi = 0; mi < 4; mi++) {
                uint32_t r0 = abase + (uint32_t)(wr * 64 + mi * 16 + (lane >> 2)) * AROWB + kb;
                a[mi][0] = lds32(r0);
                a[mi][1] = lds32(r0 + 8 * AROWB);
                a[mi][2] = lds32(r0 + 16);
                a[mi][3] = lds32(r0 + 8 * AROWB + 16);
            }
#pragma unroll
            for (int ni = 0; ni < 4; ni++) {
                uint32_t rb = bbase + (uint32_t)(wc * 32 + ni * 8 + (lane >> 2)) * AROWB + kb;
                b[ni][0] = lds32(rb);
                b[ni][1] = lds32(rb + 16);
            }
#pragma unroll
            for (int mi = 0; mi < 4; mi++)
#pragma unroll
                for (int ni = 0; ni < 4; ni++)
                    mma16816(acc[mi][ni], a[mi], b[ni]);
        }
    }

    // epilogue: bias + direct STG (float2 per quad-pair)
    const int ccol = n0 + wc * 32 + (lane & 3) * 2;
    float bvv[4][2];
#pragma unroll
    for (int ni = 0; ni < 4; ni++) {
        bvv[ni][0] = bias[ccol + ni * 8];
        bvv[ni][1] = bias[ccol + ni * 8 + 1];
    }
    const int crow = m0 + wr * 64 + (lane >> 2);
#pragma unroll
    for (int mi = 0; mi < 4; mi++) {
#pragma unroll
        for (int hf = 0; hf < 2; hf++) {
            float* cp = C + (size_t)(crow + mi * 16 + hf * 8) * Ntot + ccol;
#pragma unroll
            for (int ni = 0; ni < 4; ni++) {
                float2 v = make_float2(acc[mi][ni][hf * 2] + bvv[ni][0],
                                       acc[mi][ni][hf * 2 + 1] + bvv[ni][1]);
                *(float2*)(cp + ni * 8) = v;
            }
        }
    }
}

// ---------------- attention -------------------------------------------------
__global__ __launch_bounds__(256) void attn_kernel(const float* __restrict__ bk,
                                                   const float* __restrict__ bv) {
    const int gw = (blockIdx.x * 256 + threadIdx.x) >> 5;
    const int lane = threadIdx.x & 31;
    const int s = gw & (SS - 1);
    const int h = (gw >> 11) & (HH - 1);
    const int b = gw >> 15;
    const int e0 = (h << 6) + lane, e1 = e0 + 32;

    const float* qrow = g_C1 + (size_t)s * 3072;
    const float q0 = qrow[e0], q1 = qrow[e1];

    float sc[33];
#pragma unroll
    for (int k = 0; k < WW; k++) {
        const int t = s + k - 15;
        float k0, k1;
        if ((unsigned)t < SS) {
            const float* kr = g_C3 + (size_t)((b << 11) + t) * 2048;
            k0 = kr[e0]; k1 = kr[e1];
        } else { k0 = bk[e0]; k1 = bk[e1]; }
        float p = q0 * k0 + q1 * k1;
#pragma unroll
        for (int o = 16; o; o >>= 1) p += __shfl_xor_sync(0xffffffffu, p, o);
        sc[k] = p * 0.125f;
    }
    {
        const float* kr = g_C2 + (size_t)s * 2048;
        float p = q0 * kr[e0] + q1 * kr[e1];
#pragma unroll
        for (int o = 16; o; o >>= 1) p += __shfl_xor_sync(0xffffffffu, p, o);
        sc[31] = p * 0.125f;
    }
    {
        const float* kr = g_C1 + (size_t)s * 3072 + 1024;
        float p = q0 * kr[e0] + q1 * kr[e1];
#pragma unroll
        for (int o = 16; o; o >>= 1) p += __shfl_xor_sync(0xffffffffu, p, o);
        sc[32] = p * 0.125f;
    }

    float m = sc[0];
#pragma unroll
    for (int k = 1; k < 33; k++) m = fmaxf(m, sc[k]);
    float denom = 0.f;
#pragma unroll
    for (int k = 0; k < 33; k++) { sc[k] = expf(sc[k] - m); denom += sc[k]; }
    const float inv = 1.f / denom;

    float o0 = 0.f, o1 = 0.f;
#pragma unroll
    for (int k = 0; k < WW; k++) {
        const int t = s + k - 15;
        float v0, v1;
        if ((unsigned)t < SS) {
            const float* vr = g_C3 + (size_t)((b << 11) + t) * 2048 + 1024;
            v0 = vr[e0]; v1 = vr[e1];
        } else { v0 = bv[e0]; v1 = bv[e1]; }
        o0 += sc[k] * v0; o1 += sc[k] * v1;
    }
    {
        const float* vr = g_C2 + (size_t)s * 2048 + 1024;
        o0 += sc[31] * vr[e0]; o1 += sc[31] * vr[e1];
    }
    {
        const float* vr = g_C1 + (size_t)s * 3072 + 2048;
        o0 += sc[32] * vr[e0]; o1 += sc[32] * vr[e1];
    }
    float* orow = g_att + (size_t)((b << 11) + s) * 1024;
    orow[e0] = o0 * inv;
    orow[e1] = o1 * inv;
}

// ---------------- launch ----------------------------------------------------
extern "C" void kernel_launch(void* const* d_in, const int* in_sizes, int n_in,
                              void* d_out, int out_size) {
    const float* x   = (const float*)d_in[0];
    const float* fsq = (const float*)d_in[1];
    const float* pos = (const float*)d_in[2];
    const float* Wq  = (const float*)d_in[3];
    const float* bq  = (const float*)d_in[4];
    const float* Wk  = (const float*)d_in[5];
    const float* bk  = (const float*)d_in[6];
    const float* Wv  = (const float*)d_in[7];
    const float* bv  = (const float*)d_in[8];
    const float* Wo  = (const float*)d_in[9];
    const float* bo  = (const float*)d_in[10];
    float* out = (float*)d_out;

    __nv_bfloat16 *afsq, *apos, *ax, *aatt, *bqkv, *bov;
    float *C1, *C2, *C3, *att, *bias3;
    cudaGetSymbolAddress((void**)&afsq, g_afsq);
    cudaGetSymbolAddress((void**)&apos, g_apos);
    cudaGetSymbolAddress((void**)&ax,   g_ax);
    cudaGetSymbolAddress((void**)&aatt, g_aatt);
    cudaGetSymbolAddress((void**)&bqkv, g_bqkv);
    cudaGetSymbolAddress((void**)&bov,  g_bo);
    cudaGetSymbolAddress((void**)&C1,   g_C1);
    cudaGetSymbolAddress((void**)&C2,   g_C2);
    cudaGetSymbolAddress((void**)&C3,   g_C3);
    cudaGetSymbolAddress((void**)&att,  g_att);
    cudaGetSymbolAddress((void**)&bias3, g_bias3);

    static bool attr_set = false;
    if (!attr_set) {
        cudaFuncSetAttribute(gemm_bf16i, cudaFuncAttributeMaxDynamicSharedMemorySize,
                             STAGES * STAGE2);
        attr_set = true;
    }
    const size_t SMEM = STAGES * STAGE2;

    fuse_bias<<<12, 256>>>(bq, bk, bv);
    split_wqkv<<<1536, 256>>>(Wq, Wk, Wv);
    split_wo<<<512, 256>>>(Wo);
    split_a<<<1024, 256>>>(fsq, afsq);
    split_a<<<1024, 256>>>(pos, apos);
    split_a<<<2048, 256>>>(x, ax);

    gemm_bf16i<<<dim3(24, 16), 256, SMEM>>>(afsq, bqkv, bias3, C1, 3072);
    gemm_bf16i<<<dim3(16, 16), 256, SMEM>>>(apos, bqkv + (size_t)1024 * K2,
                                            bias3 + 1024, C2, 2048);
    gemm_bf16i<<<dim3(16, 32), 256, SMEM>>>(ax, bqkv + (size_t)1024 * K2,
                                            bias3 + 1024, C3, 2048);

    attn_kernel<<<8192, 256>>>(bk, bv);

    split_a<<<2048, 256>>>(att, aatt);
    gemm_bf16i<<<dim3(8, 32), 256, SMEM>>>(aatt, bov, bo, out, 1024);
}